// round 4
// baseline (speedup 1.0000x reference)
#include <cuda_runtime.h>
#include <cstdint>
#include <cstddef>

#define DM 19
#define HID 512
#define NH 8
#define DH 64
#define BB 16
#define LL 1024
#define NTOK (BB*LL)

#define OUT_ELEMS   (NTOK*DM)                 // 311296
#define ATTN_ELEMS  ((size_t)BB*NH*LL*LL)     // 134217728

// ---- scratch (static device arrays; allocation-free) ----
__device__ float g_q[(size_t)BB*NH*LL*DH];    // [bh][l][d]
__device__ float g_k[(size_t)BB*NH*LL*DH];
__device__ float g_v[(size_t)BB*NH*LL*DH];
__device__ float g_ctx[(size_t)NTOK*HID];     // [n][512]

// =====================================================================
// Kernel 1: QKV projections.  X[B,L,19] @ W[19,512] + b -> [bh][l][64]
// grid (512, 3), block 256
// =====================================================================
__global__ void proj_kernel(const float* __restrict__ Xq, const float* __restrict__ Xk,
                            const float* __restrict__ Xv,
                            const float* __restrict__ Wq, const float* __restrict__ Wk,
                            const float* __restrict__ Wv,
                            const float* __restrict__ bq, const float* __restrict__ bk,
                            const float* __restrict__ bv) {
    __shared__ float sW[DM*HID];      // 38912 B
    __shared__ float sX[32*20];       // 32 rows, pitch 20
    const int which = blockIdx.y;
    const float* X    = (which == 0) ? Xq : (which == 1) ? Xk : Xv;
    const float* W    = (which == 0) ? Wq : (which == 1) ? Wk : Wv;
    const float* bias = (which == 0) ? bq : (which == 1) ? bk : bv;
    float* dst        = (which == 0) ? g_q : (which == 1) ? g_k : g_v;

    const int t = threadIdx.x;
    for (int i = t; i < DM*HID; i += 256) sW[i] = W[i];
    const int base = blockIdx.x * 32;    // token base (32 divides 1024 -> one batch)
    for (int i = t; i < 32*DM; i += 256) {
        int r = i / DM, m = i - r*DM;
        sX[r*20 + m] = X[(size_t)(base + r)*DM + m];
    }
    __syncthreads();

    const int bidx = base >> 10;
    const int lbase = base & 1023;
    #pragma unroll
    for (int cc = 0; cc < 2; cc++) {
        const int c = t + cc*256;          // 0..511
        const int h = c >> 6, d = c & 63;
        float* dp = dst + ((size_t)(bidx*NH + h)*LL + lbase)*DH + d;
        const float bval = bias[c];
        for (int r = 0; r < 32; r++) {
            float acc = bval;
            #pragma unroll
            for (int m = 0; m < DM; m++) acc += sX[r*20 + m] * sW[m*HID + c];
            dp[(size_t)r*DH] = acc;
        }
    }
}

// =====================================================================
// Kernel 2: fused attention for one (b,h) x 32-query tile.
//  S[32][1024] strip in SMEM: scores -> mask -> softmax(write attn) -> PV
// grid (32, 128), block 256, dynamic smem 157184 B
// =====================================================================
#define TP 68          // padded pitch for q/k/v tiles (16B aligned)
#define MQ 32

__global__ void attn_kernel(const int* __restrict__ mask,
                            float* __restrict__ attn_out) {
    extern __shared__ float sm[];
    float* S  = sm;                      // MQ*1024
    float* qs = sm + MQ*1024;            // MQ*TP
    float* kv = qs + MQ*TP;              // 64*TP
    __shared__ float sinv[MQ];

    const int t = threadIdx.x;
    const int bh = blockIdx.y;
    const int b  = bh >> 3;
    const int h  = bh & 7;
    const int qbase = blockIdx.x * MQ;

    const float* gq = g_q + ((size_t)bh*LL + qbase)*DH;
    const float* gk = g_k + (size_t)bh*LL*DH;
    const float* gv = g_v + (size_t)bh*LL*DH;

    // load q tile
    for (int i = t; i < MQ*DH/4; i += 256) {
        int r = i >> 4, d = (i & 15)*4;
        *(float4*)(qs + r*TP + d) = *(const float4*)(gq + (size_t)r*DH + d);
    }

    const int tq = t >> 4, tk = t & 15;
    const int q0 = 2*tq, k0 = 4*tk;
    const float INVSCALE = 0.13258252147247766f;   // sqrt(9/512)

    // ---------- scores ----------
    for (int kt = 0; kt < 16; kt++) {
        __syncthreads();
        for (int i = t; i < 64*DH/4; i += 256) {
            int r = i >> 4, d = (i & 15)*4;
            *(float4*)(kv + r*TP + d) = *(const float4*)(gk + (size_t)(kt*64 + r)*DH + d);
        }
        __syncthreads();

        float acc0[4] = {0.f,0.f,0.f,0.f};
        float acc1[4] = {0.f,0.f,0.f,0.f};
        #pragma unroll 8
        for (int d0 = 0; d0 < DH; d0 += 4) {
            float4 a0 = *(float4*)(qs + q0*TP + d0);
            float4 a1 = *(float4*)(qs + (q0+1)*TP + d0);
            #pragma unroll
            for (int j = 0; j < 4; j++) {
                float4 kb = *(float4*)(kv + (k0+j)*TP + d0);
                acc0[j] += a0.x*kb.x + a0.y*kb.y + a0.z*kb.z + a0.w*kb.w;
                acc1[j] += a1.x*kb.x + a1.y*kb.y + a1.z*kb.z + a1.w*kb.w;
            }
        }
        const int kg = kt*64 + k0;
        // mask arrives as int32 (harness converts bool -> int32)
        int4 m0 = *(const int4*)(mask + ((size_t)b*LL + qbase + q0)*LL + kg);
        int4 m1 = *(const int4*)(mask + ((size_t)b*LL + qbase + q0 + 1)*LL + kg);
        float* s0 = S + q0*1024 + kg;
        float* s1 = s0 + 1024;
        s0[0] = m0.x ? -1e9f : acc0[0]*INVSCALE;
        s0[1] = m0.y ? -1e9f : acc0[1]*INVSCALE;
        s0[2] = m0.z ? -1e9f : acc0[2]*INVSCALE;
        s0[3] = m0.w ? -1e9f : acc0[3]*INVSCALE;
        s1[0] = m1.x ? -1e9f : acc1[0]*INVSCALE;
        s1[1] = m1.y ? -1e9f : acc1[1]*INVSCALE;
        s1[2] = m1.z ? -1e9f : acc1[2]*INVSCALE;
        s1[3] = m1.w ? -1e9f : acc1[3]*INVSCALE;
    }
    __syncthreads();

    // ---------- softmax (warp per 4 rows); keep raw exp in S, write attn ----------
    const int warp = t >> 5, lane = t & 31;
    for (int rr = 0; rr < 4; rr++) {
        const int row = warp*4 + rr;
        float* Sr = S + row*1024;
        float m = -1e30f;
        for (int i = lane; i < 1024; i += 32) m = fmaxf(m, Sr[i]);
        #pragma unroll
        for (int o = 16; o; o >>= 1) m = fmaxf(m, __shfl_xor_sync(~0u, m, o));
        float sum = 0.f;
        for (int i = lane; i < 1024; i += 32) {
            float e = __expf(Sr[i] - m);
            Sr[i] = e;
            sum += e;
        }
        #pragma unroll
        for (int o = 16; o; o >>= 1) sum += __shfl_xor_sync(~0u, sum, o);
        const float inv = 1.0f / sum;
        if (lane == 0) sinv[row] = inv;
        __syncwarp();
        float* arow = attn_out + ((size_t)bh*LL + qbase + row)*LL;
        for (int i = lane*4; i < 1024; i += 128) {
            float4 e4 = *(float4*)(Sr + i);
            float4 p; p.x = e4.x*inv; p.y = e4.y*inv; p.z = e4.z*inv; p.w = e4.w*inv;
            *(float4*)(arow + i) = p;
        }
    }

    // ---------- PV: ctx[32][64] = S(raw exp) @ V, scaled by sinv at end ----------
    const int pd = tk*4;
    float c0[4] = {0.f,0.f,0.f,0.f};
    float c1[4] = {0.f,0.f,0.f,0.f};
    for (int kt = 0; kt < 16; kt++) {
        __syncthreads();
        for (int i = t; i < 64*DH/4; i += 256) {
            int r = i >> 4, d = (i & 15)*4;
            *(float4*)(kv + r*TP + d) = *(const float4*)(gv + (size_t)(kt*64 + r)*DH + d);
        }
        __syncthreads();
        const float* Sr0 = S + q0*1024 + kt*64;
        const float* Sr1 = Sr0 + 1024;
        #pragma unroll 8
        for (int kk = 0; kk < 64; kk++) {
            float p0 = Sr0[kk], p1 = Sr1[kk];
            float4 vv = *(float4*)(kv + kk*TP + pd);
            c0[0] += p0*vv.x; c0[1] += p0*vv.y; c0[2] += p0*vv.z; c0[3] += p0*vv.w;
            c1[0] += p1*vv.x; c1[1] += p1*vv.y; c1[2] += p1*vv.z; c1[3] += p1*vv.w;
        }
    }
    const float i0 = sinv[q0], i1 = sinv[q0+1];
    const size_t n0 = (size_t)b*LL + qbase + q0;
    float4 o0 = make_float4(c0[0]*i0, c0[1]*i0, c0[2]*i0, c0[3]*i0);
    float4 o1 = make_float4(c1[0]*i1, c1[1]*i1, c1[2]*i1, c1[3]*i1);
    *(float4*)(g_ctx + n0*HID + h*DH + pd)     = o0;
    *(float4*)(g_ctx + (n0+1)*HID + h*DH + pd) = o1;
}

// =====================================================================
// Kernel 3: out = LN(ctx @ Wo + bo + residual). block 128 (4 rows), grid 4096
// =====================================================================
__global__ void outproj_kernel(const float* __restrict__ Qin, const float* __restrict__ Wo,
                               const float* __restrict__ bo, const float* __restrict__ lng,
                               const float* __restrict__ lnb, float* __restrict__ out) {
    __shared__ float sWo[HID*DM];    // 38912 B
    __shared__ float scx[4*HID];     // 8192 B
    __shared__ float sx[4*20];
    const int t = threadIdx.x, warp = t >> 5, lane = t & 31;
    for (int i = t; i < HID*DM; i += 128) sWo[i] = Wo[i];
    const int n = blockIdx.x*4 + warp;
    #pragma unroll
    for (int k = 0; k < 4; k++)
        *(float4*)(scx + warp*HID + lane*4 + 128*k) =
            *(const float4*)(g_ctx + (size_t)n*HID + lane*4 + 128*k);
    __syncthreads();

    float x = 0.f;
    if (lane < DM) {
        float a0 = 0.f, a1 = 0.f, a2 = 0.f, a3 = 0.f;
        const float* cs = scx + warp*HID;
        for (int i = 0; i < HID; i += 4) {
            a0 += cs[i+0]*sWo[(i+0)*DM + lane];
            a1 += cs[i+1]*sWo[(i+1)*DM + lane];
            a2 += cs[i+2]*sWo[(i+2)*DM + lane];
            a3 += cs[i+3]*sWo[(i+3)*DM + lane];
        }
        x = (a0+a1) + (a2+a3) + bo[lane] + Qin[(size_t)n*DM + lane];
        sx[warp*20 + lane] = x;
    }
    __syncwarp();
    if (lane < DM) {
        float mu = 0.f;
        #pragma unroll
        for (int j = 0; j < DM; j++) mu += sx[warp*20 + j];
        mu *= (1.0f/19.0f);
        float var = 0.f;
        #pragma unroll
        for (int j = 0; j < DM; j++) { float d = sx[warp*20 + j] - mu; var += d*d; }
        var *= (1.0f/19.0f);
        out[(size_t)n*DM + lane] = (x - mu)*rsqrtf(var + 1e-5f)*lng[lane] + lnb[lane];
    }
}

// =====================================================================
// Kernel 4: residual = Q (third tuple member)
// =====================================================================
__global__ void copy_res_kernel(const float* __restrict__ Qin, float* __restrict__ dst) {
    const size_t i = ((size_t)blockIdx.x*256 + threadIdx.x)*4;
    *(float4*)(dst + i) = *(const float4*)(Qin + i);
}

// =====================================================================
extern "C" void kernel_launch(void* const* d_in, const int* in_sizes, int n_in,
                              void* d_out, int out_size) {
    const float* Q   = (const float*)d_in[0];
    const float* K   = (const float*)d_in[1];
    const float* V   = (const float*)d_in[2];
    const int*  mask = (const int*)d_in[3];     // bool -> int32 in harness
    const float* Wq  = (const float*)d_in[4];
    const float* bq  = (const float*)d_in[5];
    const float* Wk  = (const float*)d_in[6];
    const float* bk  = (const float*)d_in[7];
    const float* Wv  = (const float*)d_in[8];
    const float* bv  = (const float*)d_in[9];
    const float* Wo  = (const float*)d_in[10];
    const float* bo  = (const float*)d_in[11];
    const float* lng = (const float*)d_in[12];
    const float* lnb = (const float*)d_in[13];

    float* out  = (float*)d_out;                 // [B,L,19]
    float* attn = out + OUT_ELEMS;               // [B,H,L,L]
    float* res  = attn + ATTN_ELEMS;             // [B,L,19]

    const int ATT_SMEM = (MQ*1024 + MQ*TP + 64*TP) * (int)sizeof(float);  // 157184
    cudaFuncSetAttribute(attn_kernel, cudaFuncAttributeMaxDynamicSharedMemorySize, ATT_SMEM);

    proj_kernel<<<dim3(NTOK/32, 3), 256>>>(Q, K, V, Wq, Wk, Wv, bq, bk, bv);
    attn_kernel<<<dim3(LL/MQ, BB*NH), 256, ATT_SMEM>>>(mask, attn);
    outproj_kernel<<<NTOK/4, 128>>>(Q, Wo, bo, lng, lnb, out);
    copy_res_kernel<<<OUT_ELEMS/4/256, 256>>>(Q, res);
}

// round 5
// speedup vs baseline: 3.2039x; 3.2039x over previous
#include <cuda_runtime.h>
#include <cstdint>
#include <cstddef>

#define DM 19
#define HID 512
#define NH 8
#define DH 64
#define BB 16
#define LL 1024
#define NTOK (BB*LL)

#define OUT_ELEMS   (NTOK*DM)
#define ATTN_ELEMS  ((size_t)BB*NH*LL*LL)

// ---- scratch ----
__device__ float g_q [(size_t)BB*NH*LL*DH];   // [bh][l][d]
__device__ float g_k [(size_t)BB*NH*LL*DH];   // [bh][l][d]
__device__ float g_kT[(size_t)BB*NH*DH*LL];   // [bh][d][l]
__device__ float g_v [(size_t)BB*NH*LL*DH];   // [bh][l][d]
__device__ float g_ctx[(size_t)NTOK*HID];     // [n][512]

// =====================================================================
// Kernel 1: QKV projections
// =====================================================================
__global__ void proj_kernel(const float* __restrict__ Xq, const float* __restrict__ Xk,
                            const float* __restrict__ Xv,
                            const float* __restrict__ Wq, const float* __restrict__ Wk,
                            const float* __restrict__ Wv,
                            const float* __restrict__ bq, const float* __restrict__ bk,
                            const float* __restrict__ bv) {
    __shared__ float sW[DM*HID];
    __shared__ float sX[32*20];
    const int which = blockIdx.y;
    const float* X    = (which == 0) ? Xq : (which == 1) ? Xk : Xv;
    const float* W    = (which == 0) ? Wq : (which == 1) ? Wk : Wv;
    const float* bias = (which == 0) ? bq : (which == 1) ? bk : bv;
    float* dst        = (which == 0) ? g_q : (which == 1) ? g_k : g_v;

    const int t = threadIdx.x;
    for (int i = t; i < DM*HID; i += 256) sW[i] = W[i];
    const int base = blockIdx.x * 32;
    for (int i = t; i < 32*DM; i += 256) {
        int r = i / DM, m = i - r*DM;
        sX[r*20 + m] = X[(size_t)(base + r)*DM + m];
    }
    __syncthreads();

    const int bidx = base >> 10;
    const int lbase = base & 1023;
    #pragma unroll
    for (int cc = 0; cc < 2; cc++) {
        const int c = t + cc*256;
        const int h = c >> 6, d = c & 63;
        float* dp = dst + ((size_t)(bidx*NH + h)*LL + lbase)*DH + d;
        const float bval = bias[c];
        for (int r = 0; r < 32; r++) {
            float acc = bval;
            #pragma unroll
            for (int m = 0; m < DM; m++) acc += sX[r*20 + m] * sW[m*HID + c];
            dp[(size_t)r*DH] = acc;
        }
    }
}

// =====================================================================
// Kernel 1b: K transpose  g_k[bh][l][d] -> g_kT[bh][d][l]
// grid (8, 128), block 256
// =====================================================================
__global__ void transpose_k_kernel() {
    __shared__ float ts[128*65];
    const int t = threadIdx.x;
    const int bh = blockIdx.y;
    const int lbase = blockIdx.x * 128;
    const float* src = g_k + ((size_t)bh*LL + lbase)*DH;
    #pragma unroll
    for (int j = 0; j < 8; j++) {
        int idx = t + j*256;
        int r = idx >> 4, d4 = (idx & 15)*4;
        float4 a = *(const float4*)(src + (size_t)r*DH + d4);
        ts[r*65 + d4 + 0] = a.x; ts[r*65 + d4 + 1] = a.y;
        ts[r*65 + d4 + 2] = a.z; ts[r*65 + d4 + 3] = a.w;
    }
    __syncthreads();
    float* dstb = g_kT + (size_t)bh*DH*LL + lbase;
    #pragma unroll
    for (int j = 0; j < 8; j++) {
        int idx = t + j*256;
        int d = idx >> 5, c = (idx & 31)*4;
        float4 o;
        o.x = ts[(c+0)*65 + d]; o.y = ts[(c+1)*65 + d];
        o.z = ts[(c+2)*65 + d]; o.w = ts[(c+3)*65 + d];
        *(float4*)(dstb + (size_t)d*LL + c) = o;
    }
}

// =====================================================================
// Kernel 2: fused attention, one (b,h) x 32-query strip.
// S[32][1024] in smem. Scores use transposed K tiles (conflict-free LDS),
// 4q x 4k register tile; PV uses 4q x 4d tile with half-split kk range.
// grid (32, 128), block 256
// =====================================================================
#define MQ 32
#define KTILE 128
#define NKT (LL/KTILE)      // 8
#define KP 128              // kT tile pitch (floats)
#define VP 68               // v tile pitch (floats)

__global__ __launch_bounds__(256, 1)
void attn_kernel(const int* __restrict__ mask, float* __restrict__ attn_out) {
    extern __shared__ float sm[];
    float* S    = sm;                       // 32*1024          = 32768 f
    float* kv   = S  + MQ*LL;               // max(64*128,128*68)= 8704 f
    float* qT   = kv + KTILE*VP;            // 64*32            = 2048 f
    float* cbuf = qT + DH*32;               // 32*68            = 2176 f
    __shared__ float sinv[MQ];

    const int t = threadIdx.x;
    const int warp = t >> 5, lane = t & 31;
    const int bh = blockIdx.y, b = bh >> 3, h = bh & 7;
    const int qbase = blockIdx.x * MQ;

    const float* gq  = g_q  + ((size_t)bh*LL + qbase)*DH;
    const float* gkT = g_kT + (size_t)bh*DH*LL;
    const float* gv  = g_v  + (size_t)bh*LL*DH;

    // build qT[d][q]  (pitch 32)
    {
        int r = t >> 3, d0 = (t & 7)*8;
        float4 a = *(const float4*)(gq + (size_t)r*DH + d0);
        float4 b4 = *(const float4*)(gq + (size_t)r*DH + d0 + 4);
        qT[(d0+0)*32 + r] = a.x;  qT[(d0+1)*32 + r] = a.y;
        qT[(d0+2)*32 + r] = a.z;  qT[(d0+3)*32 + r] = a.w;
        qT[(d0+4)*32 + r] = b4.x; qT[(d0+5)*32 + r] = b4.y;
        qT[(d0+6)*32 + r] = b4.z; qT[(d0+7)*32 + r] = b4.w;
    }

    const int q0 = 4*warp;          // warp owns 4 q rows
    const int k0 = 4*lane;          // lane owns 4 k cols within tile
    const float INVSCALE = 0.13258252147247766f;   // sqrt(9/512)

    // ---------------- scores ----------------
    float4 pf[8];
    #pragma unroll
    for (int j = 0; j < 8; j++) {
        int idx = t + j*256; int d = idx >> 5, c = (idx & 31)*4;
        pf[j] = *(const float4*)(gkT + (size_t)d*LL + c);
    }
    for (int kt = 0; kt < NKT; kt++) {
        __syncthreads();                       // buffer free (also covers qT, iter 0)
        #pragma unroll
        for (int j = 0; j < 8; j++) {
            int idx = t + j*256; int d = idx >> 5, c = (idx & 31)*4;
            *(float4*)(kv + d*KP + c) = pf[j];
        }
        __syncthreads();
        if (kt + 1 < NKT) {
            const int kb2 = (kt+1)*KTILE;
            #pragma unroll
            for (int j = 0; j < 8; j++) {
                int idx = t + j*256; int d = idx >> 5, c = (idx & 31)*4;
                pf[j] = *(const float4*)(gkT + (size_t)d*LL + kb2 + c);
            }
        }
        const int kb = kt*KTILE;
        int4 m[4];
        #pragma unroll
        for (int i = 0; i < 4; i++)
            m[i] = *(const int4*)(mask + ((size_t)b*LL + qbase + q0 + i)*LL + kb + k0);

        float acc[4][4] = {};
        #pragma unroll 8
        for (int d = 0; d < DH; d++) {
            float4 qv = *(const float4*)(qT + d*32 + q0);   // broadcast
            float4 kk = *(const float4*)(kv + d*KP + k0);   // conflict-free
            acc[0][0] += qv.x*kk.x; acc[0][1] += qv.x*kk.y; acc[0][2] += qv.x*kk.z; acc[0][3] += qv.x*kk.w;
            acc[1][0] += qv.y*kk.x; acc[1][1] += qv.y*kk.y; acc[1][2] += qv.y*kk.z; acc[1][3] += qv.y*kk.w;
            acc[2][0] += qv.z*kk.x; acc[2][1] += qv.z*kk.y; acc[2][2] += qv.z*kk.z; acc[2][3] += qv.z*kk.w;
            acc[3][0] += qv.w*kk.x; acc[3][1] += qv.w*kk.y; acc[3][2] += qv.w*kk.z; acc[3][3] += qv.w*kk.w;
        }
        #pragma unroll
        for (int i = 0; i < 4; i++) {
            float4 s;
            s.x = m[i].x ? -1e9f : acc[i][0]*INVSCALE;
            s.y = m[i].y ? -1e9f : acc[i][1]*INVSCALE;
            s.z = m[i].z ? -1e9f : acc[i][2]*INVSCALE;
            s.w = m[i].w ? -1e9f : acc[i][3]*INVSCALE;
            *(float4*)(S + (q0+i)*LL + kb + k0) = s;
        }
    }
    __syncthreads();

    // ---------------- softmax: raw exp kept in S, normalized attn written out ----------------
    for (int rr = 0; rr < 4; rr++) {
        const int row = warp*4 + rr;
        float* Sr = S + row*LL;
        float mx = -1e30f;
        for (int i = lane; i < LL; i += 32) mx = fmaxf(mx, Sr[i]);
        #pragma unroll
        for (int o = 16; o; o >>= 1) mx = fmaxf(mx, __shfl_xor_sync(~0u, mx, o));
        float sum = 0.f;
        for (int i = lane; i < LL; i += 32) {
            float e = __expf(Sr[i] - mx);
            Sr[i] = e;
            sum += e;
        }
        #pragma unroll
        for (int o = 16; o; o >>= 1) sum += __shfl_xor_sync(~0u, sum, o);
        const float inv = 1.0f / sum;
        if (lane == 0) sinv[row] = inv;
        __syncwarp();
        float* arow = attn_out + ((size_t)bh*LL + qbase + row)*LL;
        for (int i = lane*4; i < LL; i += 128) {
            float4 e4 = *(float4*)(Sr + i);
            float4 p; p.x = e4.x*inv; p.y = e4.y*inv; p.z = e4.z*inv; p.w = e4.w*inv;
            *(float4*)(arow + i) = p;
        }
    }

    // ---------------- PV: ctx[32][64] = (raw-exp S) @ V, scale by sinv at end ----------------
    // thread: warp -> 4 q rows; lane: half = lane>>4 (kk half), dg = lane&15 -> 4 d cols
    const int half = lane >> 4;
    const int pd = 4*(lane & 15);
    float c[4][4] = {};

    #pragma unroll
    for (int j = 0; j < 8; j++) {
        int idx = t + j*256; int r = idx >> 4, d4 = (idx & 15)*4;
        pf[j] = *(const float4*)(gv + (size_t)r*DH + d4);
    }
    for (int kt = 0; kt < NKT; kt++) {
        __syncthreads();
        #pragma unroll
        for (int j = 0; j < 8; j++) {
            int idx = t + j*256; int r = idx >> 4, d4 = (idx & 15)*4;
            *(float4*)(kv + r*VP + d4) = pf[j];
        }
        __syncthreads();
        if (kt + 1 < NKT) {
            const int kb2 = (kt+1)*KTILE;
            #pragma unroll
            for (int j = 0; j < 8; j++) {
                int idx = t + j*256; int r = idx >> 4, d4 = (idx & 15)*4;
                pf[j] = *(const float4*)(gv + (size_t)(kb2 + r)*DH + d4);
            }
        }
        const float* Sr0 = S + (q0+0)*LL + kt*KTILE + half*64;
        const float* Sr1 = S + (q0+1)*LL + kt*KTILE + half*64;
        const float* Sr2 = S + (q0+2)*LL + kt*KTILE + half*64;
        const float* Sr3 = S + (q0+3)*LL + kt*KTILE + half*64;
        const float* vb = kv + half*64*VP + pd;
        #pragma unroll 4
        for (int kk = 0; kk < 64; kk += 2) {
            float4 v0 = *(const float4*)(vb + kk*VP);
            float4 v1 = *(const float4*)(vb + (kk+1)*VP);
            float2 s0 = *(const float2*)(Sr0 + kk);
            float2 s1 = *(const float2*)(Sr1 + kk);
            float2 s2 = *(const float2*)(Sr2 + kk);
            float2 s3 = *(const float2*)(Sr3 + kk);
            c[0][0] += s0.x*v0.x + s0.y*v1.x; c[0][1] += s0.x*v0.y + s0.y*v1.y;
            c[0][2] += s0.x*v0.z + s0.y*v1.z; c[0][3] += s0.x*v0.w + s0.y*v1.w;
            c[1][0] += s1.x*v0.x + s1.y*v1.x; c[1][1] += s1.x*v0.y + s1.y*v1.y;
            c[1][2] += s1.x*v0.z + s1.y*v1.z; c[1][3] += s1.x*v0.w + s1.y*v1.w;
            c[2][0] += s2.x*v0.x + s2.y*v1.x; c[2][1] += s2.x*v0.y + s2.y*v1.y;
            c[2][2] += s2.x*v0.z + s2.y*v1.z; c[2][3] += s2.x*v0.w + s2.y*v1.w;
            c[3][0] += s3.x*v0.x + s3.y*v1.x; c[3][1] += s3.x*v0.y + s3.y*v1.y;
            c[3][2] += s3.x*v0.z + s3.y*v1.z; c[3][3] += s3.x*v0.w + s3.y*v1.w;
        }
    }
    // reduce the two kk-halves through cbuf
    __syncthreads();
    if (half == 0) {
        #pragma unroll
        for (int i = 0; i < 4; i++)
            *(float4*)(cbuf + (q0+i)*VP + pd) = make_float4(c[i][0], c[i][1], c[i][2], c[i][3]);
    }
    __syncthreads();
    if (half == 1) {
        #pragma unroll
        for (int i = 0; i < 4; i++) {
            float4 o = *(float4*)(cbuf + (q0+i)*VP + pd);
            o.x += c[i][0]; o.y += c[i][1]; o.z += c[i][2]; o.w += c[i][3];
            *(float4*)(cbuf + (q0+i)*VP + pd) = o;
        }
    }
    __syncthreads();
    // final write with 1/sum scale
    {
        const int row = t >> 3, c8 = (t & 7)*8;
        const float iv = sinv[row];
        float4 a = *(float4*)(cbuf + row*VP + c8);
        float4 b4 = *(float4*)(cbuf + row*VP + c8 + 4);
        a.x *= iv; a.y *= iv; a.z *= iv; a.w *= iv;
        b4.x *= iv; b4.y *= iv; b4.z *= iv; b4.w *= iv;
        float* dp = g_ctx + ((size_t)b*LL + qbase + row)*HID + h*DH + c8;
        *(float4*)(dp)     = a;
        *(float4*)(dp + 4) = b4;
    }
}

// =====================================================================
// Kernel 3: out = LN(ctx @ Wo + bo + residual)
// =====================================================================
__global__ void outproj_kernel(const float* __restrict__ Qin, const float* __restrict__ Wo,
                               const float* __restrict__ bo, const float* __restrict__ lng,
                               const float* __restrict__ lnb, float* __restrict__ out) {
    __shared__ float sWo[HID*DM];
    __shared__ float scx[4*HID];
    __shared__ float sx[4*20];
    const int t = threadIdx.x, warp = t >> 5, lane = t & 31;
    for (int i = t; i < HID*DM; i += 128) sWo[i] = Wo[i];
    const int n = blockIdx.x*4 + warp;
    #pragma unroll
    for (int k = 0; k < 4; k++)
        *(float4*)(scx + warp*HID + lane*4 + 128*k) =
            *(const float4*)(g_ctx + (size_t)n*HID + lane*4 + 128*k);
    __syncthreads();

    float x = 0.f;
    if (lane < DM) {
        float a0 = 0.f, a1 = 0.f, a2 = 0.f, a3 = 0.f;
        const float* cs = scx + warp*HID;
        for (int i = 0; i < HID; i += 4) {
            a0 += cs[i+0]*sWo[(i+0)*DM + lane];
            a1 += cs[i+1]*sWo[(i+1)*DM + lane];
            a2 += cs[i+2]*sWo[(i+2)*DM + lane];
            a3 += cs[i+3]*sWo[(i+3)*DM + lane];
        }
        x = (a0+a1) + (a2+a3) + bo[lane] + Qin[(size_t)n*DM + lane];
        sx[warp*20 + lane] = x;
    }
    __syncwarp();
    if (lane < DM) {
        float mu = 0.f;
        #pragma unroll
        for (int j = 0; j < DM; j++) mu += sx[warp*20 + j];
        mu *= (1.0f/19.0f);
        float var = 0.f;
        #pragma unroll
        for (int j = 0; j < DM; j++) { float d = sx[warp*20 + j] - mu; var += d*d; }
        var *= (1.0f/19.0f);
        out[(size_t)n*DM + lane] = (x - mu)*rsqrtf(var + 1e-5f)*lng[lane] + lnb[lane];
    }
}

// =====================================================================
// Kernel 4: residual = Q
// =====================================================================
__global__ void copy_res_kernel(const float* __restrict__ Qin, float* __restrict__ dst) {
    const size_t i = ((size_t)blockIdx.x*256 + threadIdx.x)*4;
    *(float4*)(dst + i) = *(const float4*)(Qin + i);
}

// =====================================================================
extern "C" void kernel_launch(void* const* d_in, const int* in_sizes, int n_in,
                              void* d_out, int out_size) {
    const float* Q   = (const float*)d_in[0];
    const float* K   = (const float*)d_in[1];
    const float* V   = (const float*)d_in[2];
    const int*  mask = (const int*)d_in[3];
    const float* Wq  = (const float*)d_in[4];
    const float* bq  = (const float*)d_in[5];
    const float* Wk  = (const float*)d_in[6];
    const float* bk  = (const float*)d_in[7];
    const float* Wv  = (const float*)d_in[8];
    const float* bv  = (const float*)d_in[9];
    const float* Wo  = (const float*)d_in[10];
    const float* bo  = (const float*)d_in[11];
    const float* lng = (const float*)d_in[12];
    const float* lnb = (const float*)d_in[13];

    float* out  = (float*)d_out;
    float* attn = out + OUT_ELEMS;
    float* res  = attn + ATTN_ELEMS;

    const int ATT_SMEM = (MQ*LL + KTILE*VP + DH*32 + 32*VP) * (int)sizeof(float); // 182784
    cudaFuncSetAttribute(attn_kernel, cudaFuncAttributeMaxDynamicSharedMemorySize, ATT_SMEM);

    proj_kernel<<<dim3(NTOK/32, 3), 256>>>(Q, K, V, Wq, Wk, Wv, bq, bk, bv);
    transpose_k_kernel<<<dim3(LL/128, BB*NH), 256>>>();
    attn_kernel<<<dim3(LL/MQ, BB*NH), 256, ATT_SMEM>>>(mask, attn);
    outproj_kernel<<<NTOK/4, 128>>>(Q, Wo, bo, lng, lnb, out);
    copy_res_kernel<<<OUT_ELEMS/4/256, 256>>>(Q, res);
}